// round 1
// baseline (speedup 1.0000x reference)
#include <cuda_runtime.h>
#include <math.h>

#define H 1024
#define V 50257
#define S 4096

// -------- scratch (device globals; no allocation allowed) --------
__device__ float g_gates[4 * H];
__device__ float g_h[H];
__device__ float g_c[H];
__device__ float g_vpart[64 * H];
__device__ float g_v[H];
__device__ float g_bh;
__device__ float g_scores[S];
__device__ float g_attn[S];
__device__ float g_cpart[64 * H];
__device__ float g_feat[2 * H];
__device__ float g_logits[V];
__device__ float g_lse;

// K1: gates[r] = W_ih[r]·x + W_hh[r]·h0 + b_ih[r] + b_hh[r], x = embedding[word]
// grid 512 x 256 (8 warps/block, warp-per-row, 4096 rows)
__global__ void k_gates(const int* __restrict__ word,
                        const float* __restrict__ emb,
                        const float* __restrict__ h0,
                        const float* __restrict__ Wih,
                        const float* __restrict__ Whh,
                        const float* __restrict__ bih,
                        const float* __restrict__ bhh) {
    __shared__ float sx[H];
    __shared__ float sh[H];
    int tid = threadIdx.x;
    int w = word[0];
    for (int i = tid; i < H; i += 256) {
        sx[i] = emb[(size_t)w * H + i];
        sh[i] = h0[i];
    }
    __syncthreads();
    int lane = tid & 31;
    int warp = tid >> 5;
    int row  = blockIdx.x * 8 + warp;   // always < 4096
    const float4* wi = (const float4*)(Wih + (size_t)row * H);
    const float4* wh = (const float4*)(Whh + (size_t)row * H);
    const float4* x4 = (const float4*)sx;
    const float4* h4 = (const float4*)sh;
    float acc = 0.f;
#pragma unroll
    for (int i = lane; i < H / 4; i += 32) {
        float4 a = wi[i], b = x4[i];
        acc += a.x * b.x + a.y * b.y + a.z * b.z + a.w * b.w;
        float4 c = wh[i], d = h4[i];
        acc += c.x * d.x + c.y * d.y + c.z * d.z + c.w * d.w;
    }
#pragma unroll
    for (int o = 16; o; o >>= 1) acc += __shfl_xor_sync(0xffffffffu, acc, o);
    if (lane == 0) g_gates[row] = acc + bih[row] + bhh[row];
}

// K2: LSTM pointwise. 1 block x 1024 threads.
__global__ void k_lstm(const float* __restrict__ c0,
                       float* __restrict__ out_h, float* __restrict__ out_c) {
    int j = threadIdx.x;
    float ig = g_gates[j];
    float fg = g_gates[H + j];
    float gg = g_gates[2 * H + j];
    float og = g_gates[3 * H + j];
    float si = 1.f / (1.f + expf(-ig));
    float sf = 1.f / (1.f + expf(-fg));
    float so = 1.f / (1.f + expf(-og));
    float cn = sf * c0[j] + si * tanhf(gg);
    float hn = so * tanhf(cn);
    g_h[j] = hn;
    g_c[j] = cn;
    g_feat[j] = hn;     // first half of feat
    out_h[j] = hn;
    out_c[j] = cn;
}

// K3: partial v[k] = sum_j attn_W[j][k] * h[j]  (column reduction)
// grid 64 x 256, block b handles j in [16b, 16b+16), thread t handles k = t, t+256, t+512, t+768
__global__ void k_vpart(const float* __restrict__ attnW) {
    int t = threadIdx.x;
    int j0 = blockIdx.x * 16;
    float a0 = 0.f, a1 = 0.f, a2 = 0.f, a3 = 0.f;
#pragma unroll
    for (int jj = 0; jj < 16; ++jj) {
        int j = j0 + jj;
        float hv = g_h[j];
        const float* rp = attnW + (size_t)j * H;
        a0 += rp[t]       * hv;
        a1 += rp[t + 256] * hv;
        a2 += rp[t + 512] * hv;
        a3 += rp[t + 768] * hv;
    }
    float* dst = g_vpart + (size_t)blockIdx.x * H;
    dst[t] = a0; dst[t + 256] = a1; dst[t + 512] = a2; dst[t + 768] = a3;
}

// K4: v reduce + bh = attn_b . h. 1 block x 1024.
__global__ void k_vreduce(const float* __restrict__ attn_b) {
    __shared__ float sred[1024];
    int k = threadIdx.x;
    float acc = 0.f;
#pragma unroll 8
    for (int b = 0; b < 64; ++b) acc += g_vpart[b * H + k];
    g_v[k] = acc;
    sred[k] = attn_b[k] * g_h[k];
    __syncthreads();
    for (int o = 512; o; o >>= 1) {
        if (k < o) sred[k] += sred[k + o];
        __syncthreads();
    }
    if (k == 0) g_bh = sred[0];
}

// K5: scores[s] = enc[s] . v + bh.  grid 512 x 256, warp-per-row.
__global__ void k_scores(const float* __restrict__ enc) {
    __shared__ float sv[H];
    int tid = threadIdx.x;
    for (int i = tid; i < H; i += 256) sv[i] = g_v[i];
    __syncthreads();
    int lane = tid & 31;
    int warp = tid >> 5;
    int srow = blockIdx.x * 8 + warp;   // always < 4096
    const float4* e4 = (const float4*)(enc + (size_t)srow * H);
    const float4* v4 = (const float4*)sv;
    float acc = 0.f;
#pragma unroll
    for (int i = lane; i < H / 4; i += 32) {
        float4 a = e4[i], b = v4[i];
        acc += a.x * b.x + a.y * b.y + a.z * b.z + a.w * b.w;
    }
#pragma unroll
    for (int o = 16; o; o >>= 1) acc += __shfl_xor_sync(0xffffffffu, acc, o);
    if (lane == 0) g_scores[srow] = acc + g_bh;
}

// K6: softmax over S=4096 scores. 1 block x 1024, 4 elements/thread.
__global__ void k_attnsm(float* __restrict__ out_attn) {
    __shared__ float sred[1024];
    int t = threadIdx.x;
    float x0 = g_scores[t];
    float x1 = g_scores[t + 1024];
    float x2 = g_scores[t + 2048];
    float x3 = g_scores[t + 3072];
    float m = fmaxf(fmaxf(x0, x1), fmaxf(x2, x3));
    sred[t] = m;
    __syncthreads();
    for (int o = 512; o; o >>= 1) {
        if (t < o) sred[t] = fmaxf(sred[t], sred[t + o]);
        __syncthreads();
    }
    m = sred[0];
    __syncthreads();
    float e0 = expf(x0 - m), e1 = expf(x1 - m), e2 = expf(x2 - m), e3 = expf(x3 - m);
    sred[t] = e0 + e1 + e2 + e3;
    __syncthreads();
    for (int o = 512; o; o >>= 1) {
        if (t < o) sred[t] += sred[t + o];
        __syncthreads();
    }
    float inv = 1.f / sred[0];
    float a0 = e0 * inv, a1 = e1 * inv, a2 = e2 * inv, a3 = e3 * inv;
    g_attn[t] = a0;            out_attn[t] = a0;
    g_attn[t + 1024] = a1;     out_attn[t + 1024] = a1;
    g_attn[t + 2048] = a2;     out_attn[t + 2048] = a2;
    g_attn[t + 3072] = a3;     out_attn[t + 3072] = a3;
}

// K7: partial context[k] = sum_s attn[s] * enc[s][k].  grid 64 x 256, 64 s-rows/block.
__global__ void k_cpart(const float* __restrict__ enc) {
    int t = threadIdx.x;
    int s0 = blockIdx.x * 64;
    float a0 = 0.f, a1 = 0.f, a2 = 0.f, a3 = 0.f;
    for (int ss = 0; ss < 64; ++ss) {
        int s = s0 + ss;
        float aw = g_attn[s];
        const float* ep = enc + (size_t)s * H;
        a0 += ep[t]       * aw;
        a1 += ep[t + 256] * aw;
        a2 += ep[t + 512] * aw;
        a3 += ep[t + 768] * aw;
    }
    float* dst = g_cpart + (size_t)blockIdx.x * H;
    dst[t] = a0; dst[t + 256] = a1; dst[t + 512] = a2; dst[t + 768] = a3;
}

// K8: context reduce -> feat second half. 1 block x 1024.
__global__ void k_creduce() {
    int k = threadIdx.x;
    float acc = 0.f;
#pragma unroll 8
    for (int b = 0; b < 64; ++b) acc += g_cpart[b * H + k];
    g_feat[H + k] = acc;
}

// K9: logits[r] = out_W[r] . feat + out_b[r].  THE big one: 412 MB.
// grid 6283 x 256, warp-per-row (8 rows/block).
__global__ void k_logits(const float* __restrict__ outW,
                         const float* __restrict__ outb) {
    __shared__ float sf[2 * H];   // 8 KB
    int tid = threadIdx.x;
    for (int i = tid; i < 2 * H; i += 256) sf[i] = g_feat[i];
    __syncthreads();
    int lane = tid & 31;
    int warp = tid >> 5;
    int row  = blockIdx.x * 8 + warp;
    if (row >= V) return;
    const float4* w4 = (const float4*)(outW + (size_t)row * (2 * H));
    const float4* f4 = (const float4*)sf;
    float acc = 0.f;
#pragma unroll
    for (int i = lane; i < (2 * H) / 4; i += 32) {   // 16 iters/lane
        float4 a = w4[i], b = f4[i];
        acc += a.x * b.x + a.y * b.y + a.z * b.z + a.w * b.w;
    }
#pragma unroll
    for (int o = 16; o; o >>= 1) acc += __shfl_xor_sync(0xffffffffu, acc, o);
    if (lane == 0) g_logits[row] = acc + outb[row];
}

// K10: log-sum-exp over V logits (online, deterministic). 1 block x 1024.
__global__ void k_lse() {
    __shared__ float sm[1024];
    __shared__ float ss[1024];
    int t = threadIdx.x;
    float m = -INFINITY, s = 0.f;
    for (int i = t; i < V; i += 1024) {
        float x = g_logits[i];
        float mn = fmaxf(m, x);
        s = s * expf(m - mn) + expf(x - mn);
        m = mn;
    }
    sm[t] = m; ss[t] = s;
    __syncthreads();
    for (int o = 512; o; o >>= 1) {
        if (t < o) {
            float m2 = sm[t + o], s2 = ss[t + o];
            float mn = fmaxf(sm[t], m2);
            ss[t] = ss[t] * expf(sm[t] - mn) + s2 * expf(m2 - mn);
            sm[t] = mn;
        }
        __syncthreads();
    }
    if (t == 0) g_lse = sm[0] + logf(ss[0]);
}

// K11: final log-softmax write.
__global__ void k_final(float* __restrict__ out) {
    int t = blockIdx.x * 256 + threadIdx.x;
    if (t < V) out[t] = g_logits[t] - g_lse;
}

extern "C" void kernel_launch(void* const* d_in, const int* in_sizes, int n_in,
                              void* d_out, int out_size) {
    const int*   word   = (const int*)  d_in[0];
    const float* h0     = (const float*)d_in[1];
    const float* c0     = (const float*)d_in[2];
    const float* enc    = (const float*)d_in[3];   // (S,1,H) contiguous
    const float* emb    = (const float*)d_in[4];
    const float* Wih    = (const float*)d_in[5];
    const float* Whh    = (const float*)d_in[6];
    const float* bih    = (const float*)d_in[7];
    const float* bhh    = (const float*)d_in[8];
    const float* attnW  = (const float*)d_in[9];
    const float* attnb  = (const float*)d_in[10];
    const float* outW   = (const float*)d_in[11];
    const float* outb   = (const float*)d_in[12];

    float* out = (float*)d_out;
    // output tuple flattened: [log_softmax (V)] [h_new (H)] [c_new (H)] [attn_w (S)]
    float* o_logsm = out;
    float* o_h     = out + V;
    float* o_c     = out + V + H;
    float* o_attn  = out + V + 2 * H;

    k_gates  <<<512, 256>>>(word, emb, h0, Wih, Whh, bih, bhh);
    k_lstm   <<<1, 1024>>>(c0, o_h, o_c);
    k_vpart  <<<64, 256>>>(attnW);
    k_vreduce<<<1, 1024>>>(attnb);
    k_scores <<<512, 256>>>(enc);
    k_attnsm <<<1, 1024>>>(o_attn);
    k_cpart  <<<64, 256>>>(enc);
    k_creduce<<<1, 1024>>>();
    k_logits <<<(V + 7) / 8, 256>>>(outW, outb);
    k_lse    <<<1, 1024>>>();
    k_final  <<<(V + 255) / 256, 256>>>(o_logsm);
}